// round 12
// baseline (speedup 1.0000x reference)
#include <cuda_runtime.h>
#include <cuda_bf16.h>
#include <math.h>
#include <stdint.h>

// Problem constants
#define B_DIM  64
#define T_DIM  256
#define D_DIM  768
#define NH_DIM 12
#define DH_DIM 64
#define C_DIM  7
#define M_ROWS (B_DIM * T_DIM)   // 16384
#define NQKV   (3 * D_DIM)       // 2304
#define KB16   (D_DIM / 16)      // 48
#define MB16   (M_ROWS / 16)     // 1024
#define NBP    (NQKV / 16)       // 144  (n8-pair blocks)

// Prep-kernel block ranges
#define PA_BLOCKS  (MB16 * KB16 * 32 / 256)   // 6144
#define PW_BLOCKS  (NBP  * KB16 * 32 / 256)   // 864
#define WC_BLOCKS  24
#define PREP_BLOCKS (PA_BLOCKS + PW_BLOCKS + WC_BLOCKS)

// ---------------------------------------------------------------------------
// Scratch (device globals; no runtime allocation allowed)
// ---------------------------------------------------------------------------
__device__ __nv_bfloat16 g_Q[(size_t)M_ROWS * D_DIM];
__device__ __nv_bfloat16 g_K[(size_t)M_ROWS * D_DIM];
__device__ __nv_bfloat16 g_V[(size_t)M_ROWS * D_DIM];
__device__ __nv_bfloat16 g_CTX[(size_t)M_ROWS * D_DIM];
// A fragments: [mb16][kb16][lane][8 halves]
__device__ __nv_bfloat16 g_Abf[(size_t)MB16 * KB16 * 256];
// B fragment PAIRS: [nbp][kb16][lane][8 halves] (n8 pair 2nbp, 2nbp+1)
__device__ __nv_bfloat16 g_Wbf[(size_t)NBP * KB16 * 256];
__device__ float g_bpack[NQKV];
__device__ float g_WoWc[D_DIM * C_DIM];
__device__ float g_boWc[C_DIM];

// ---------------------------------------------------------------------------
__device__ __forceinline__ uint32_t pack_bf2(float lo, float hi) {
    __nv_bfloat162 t = __floats2bfloat162_rn(lo, hi);
    return *reinterpret_cast<uint32_t*>(&t);
}

// ---------------------------------------------------------------------------
// Fused prep: pack A fragments | pack B fragment-pairs + biases | WoWc fold.
// ---------------------------------------------------------------------------
__global__ __launch_bounds__(256)
void prep_kernel(const float* __restrict__ H,
                 const float* __restrict__ Wq, const float* __restrict__ Wk,
                 const float* __restrict__ Wv,
                 const float* __restrict__ bq, const float* __restrict__ bk,
                 const float* __restrict__ bv,
                 const float* __restrict__ Wo, const float* __restrict__ Wc,
                 const float* __restrict__ bo,
                 __nv_bfloat16* __restrict__ Abf,
                 __nv_bfloat16* __restrict__ Wbf,
                 float* __restrict__ bp,
                 float* __restrict__ WoWc, float* __restrict__ boWc)
{
    const int blk = blockIdx.x;

    if (blk < PA_BLOCKS) {
        // ---- pack A: H -> fragment-packed bf16
        const int idx  = blk * 256 + threadIdx.x;
        const int lane = idx & 31;
        const int kblk = (idx >> 5) % KB16;
        const int mblk = idx / (KB16 * 32);
        const int gid  = lane >> 2;
        const int tig  = lane & 3;
        const int m0 = mblk * 16 + gid;
        const int k0 = kblk * 16 + 2 * tig;

        float2 p00 = *(const float2*)&H[(size_t)m0 * D_DIM + k0];
        float2 p10 = *(const float2*)&H[(size_t)(m0 + 8) * D_DIM + k0];
        float2 p01 = *(const float2*)&H[(size_t)m0 * D_DIM + k0 + 8];
        float2 p11 = *(const float2*)&H[(size_t)(m0 + 8) * D_DIM + k0 + 8];

        uint4 out;
        out.x = pack_bf2(p00.x, p00.y);
        out.y = pack_bf2(p10.x, p10.y);
        out.z = pack_bf2(p01.x, p01.y);
        out.w = pack_bf2(p11.x, p11.y);
        *(uint4*)&Abf[(size_t)idx * 8] = out;

    } else if (blk < PA_BLOCKS + PW_BLOCKS) {
        // ---- pack B fragment PAIRS: n8 blocks (2nbp, 2nbp+1) interleaved
        const int idx  = (blk - PA_BLOCKS) * 256 + threadIdx.x;
        const int lane = idx & 31;
        const int kblk = (idx >> 5) % KB16;
        const int nbp  = idx / (KB16 * 32);
        const int gid  = lane >> 2;
        const int tig  = lane & 3;
        const int n0 = nbp * 16 + gid;        // first n8 block's column
        const int n1 = n0 + 8;                // second n8 block's column
        const int k0 = kblk * 16 + 2 * tig;

        const float* W = (n0 < D_DIM) ? Wq : ((n0 < 2 * D_DIM) ? Wk : Wv);
        const int mat_off = (n0 >= 2 * D_DIM) ? 2 * D_DIM
                          : ((n0 >= D_DIM) ? D_DIM : 0);
        const int j0 = n0 - mat_off;
        const int j1 = n1 - mat_off;

        uint4 out;
        out.x = pack_bf2(W[(size_t)k0 * D_DIM + j0],
                         W[(size_t)(k0 + 1) * D_DIM + j0]);
        out.y = pack_bf2(W[(size_t)(k0 + 8) * D_DIM + j0],
                         W[(size_t)(k0 + 9) * D_DIM + j0]);
        out.z = pack_bf2(W[(size_t)k0 * D_DIM + j1],
                         W[(size_t)(k0 + 1) * D_DIM + j1]);
        out.w = pack_bf2(W[(size_t)(k0 + 8) * D_DIM + j1],
                         W[(size_t)(k0 + 9) * D_DIM + j1]);
        *(uint4*)&Wbf[(size_t)idx * 8] = out;

        if (idx < NQKV) {
            float bv_;
            if (idx < D_DIM)            bv_ = bq[idx];
            else if (idx < 2 * D_DIM)   bv_ = bk[idx - D_DIM];
            else                        bv_ = bv[idx - 2 * D_DIM];
            bp[idx] = bv_;
        }

    } else {
        // ---- WoWc fold
        const int wblk   = blk - PA_BLOCKS - PW_BLOCKS;
        const int gwarp  = (wblk * 256 + threadIdx.x) >> 5;
        const int nwarps = (WC_BLOCKS * 256) >> 5;
        const int lane   = threadIdx.x & 31;

        for (int d = gwarp; d < D_DIM; d += nwarps) {
            float acc[C_DIM];
            #pragma unroll
            for (int c = 0; c < C_DIM; c++) acc[c] = 0.0f;
            for (int n = lane; n < D_DIM; n += 32) {
                const float w = Wo[(size_t)d * D_DIM + n];
                const float* wcr = &Wc[(size_t)(D_DIM + n) * C_DIM];
                #pragma unroll
                for (int c = 0; c < C_DIM; c++) acc[c] += w * wcr[c];
            }
            #pragma unroll
            for (int c = 0; c < C_DIM; c++) {
                acc[c] += __shfl_xor_sync(0xFFFFFFFFu, acc[c], 16);
                acc[c] += __shfl_xor_sync(0xFFFFFFFFu, acc[c], 8);
                acc[c] += __shfl_xor_sync(0xFFFFFFFFu, acc[c], 4);
                acc[c] += __shfl_xor_sync(0xFFFFFFFFu, acc[c], 2);
                acc[c] += __shfl_xor_sync(0xFFFFFFFFu, acc[c], 1);
            }
            if (lane == 0) {
                #pragma unroll
                for (int c = 0; c < C_DIM; c++) WoWc[d * C_DIM + c] = acc[c];
            }
        }

        const int g = wblk * 256 + threadIdx.x;
        if (g < C_DIM) {
            float a = 0.0f;
            for (int n = 0; n < D_DIM; n++)
                a += bo[n] * Wc[(size_t)(D_DIM + n) * C_DIM + g];
            boWc[g] = a;
        }
    }
}

// ---------------------------------------------------------------------------
// BF16 tensor-core GEMM v2: CTA 128x256, warp tile 64x64 (2m x 4n warps),
// BK=64 (4 kb16), 3-stage cp.async pipeline, pair-packed B (LDS.128 only).
// smem traffic per output halves vs round 10's 32x64 warp tile.
// ---------------------------------------------------------------------------
#define GBM 128
#define GBN 256
#define A_STAGE_H 8192    // 8 mb x 4 kb x 32 x 8 halves (16 KB)
#define B_STAGE_H 16384   // 16 nbp x 4 kb x 32 x 8 halves (32 KB)
#define GEMM_SMEM_BYTES (3 * (A_STAGE_H + B_STAGE_H) * 2)   // 147456

__device__ __forceinline__ void cp_async16(uint32_t smem_addr, const void* gptr) {
    asm volatile("cp.async.cg.shared.global [%0], [%1], 16;\n"
                 :: "r"(smem_addr), "l"(gptr));
}

__device__ __forceinline__ void mma_bf16(float* d, uint4 a, uint32_t b0, uint32_t b1) {
    asm volatile(
        "mma.sync.aligned.m16n8k16.row.col.f32.bf16.bf16.f32 "
        "{%0,%1,%2,%3}, {%4,%5,%6,%7}, {%8,%9}, {%0,%1,%2,%3};\n"
        : "+f"(d[0]), "+f"(d[1]), "+f"(d[2]), "+f"(d[3])
        : "r"(a.x), "r"(a.y), "r"(a.z), "r"(a.w), "r"(b0), "r"(b1));
}

__global__ __launch_bounds__(256, 1)
void bf16_gemm_kernel(const __nv_bfloat16* __restrict__ Abf,
                      const __nv_bfloat16* __restrict__ Wbf,
                      const float* __restrict__ bias,
                      __nv_bfloat16* __restrict__ C0,
                      __nv_bfloat16* __restrict__ C1,
                      __nv_bfloat16* __restrict__ C2)
{
    extern __shared__ __nv_bfloat16 smem[];
    __nv_bfloat16* As = smem;                     // [3][A_STAGE_H]
    __nv_bfloat16* Bs = smem + 3 * A_STAGE_H;     // [3][B_STAGE_H]

    const int tid  = threadIdx.x;
    const int lane = tid & 31;
    const int warp = tid >> 5;
    const int gid  = lane >> 2;
    const int tig  = lane & 3;

    const int mrow0 = blockIdx.y * 8;     // first mb16 of CTA
    const int nbp0  = blockIdx.x * 16;    // first nbp of CTA
    const int block_row = blockIdx.y * GBM;
    const int block_col = blockIdx.x * GBN;

    const int seg = block_col / D_DIM;    // GBN=256 divides 768 cleanly
    __nv_bfloat16* Cout = (seg == 0) ? C0 : (seg == 1 ? C1 : C2);
    const int out_col_base = block_col - seg * D_DIM;

    const uint32_t As_u32 = (uint32_t)__cvta_generic_to_shared(As);
    const uint32_t Bs_u32 = As_u32 + 3 * A_STAGE_H * 2;

    // warp layout: wm in {0,1} (64 rows each), wn in {0..3} (64 cols each)
    const int wm = warp & 1;
    const int wn = warp >> 1;
    const int warp_mb  = wm * 4;     // 4 mb16 blocks per warp
    const int warp_nbp = wn * 4;     // 4 nbp (=8 n8) blocks per warp

    float d[4][8][4];
    #pragma unroll
    for (int mi = 0; mi < 4; mi++)
        #pragma unroll
        for (int ni = 0; ni < 8; ni++)
            #pragma unroll
            for (int e = 0; e < 4; e++)
                d[mi][ni][e] = 0.0f;

    const int NIT = KB16 / 4;   // 12 iterations of BK=64

    // stage copy: A 1024 chunks (c = mb*128 + kbl*32 + lane),
    //             B 2048 chunks (c = nbp*128 + kbl*32 + lane)
    auto do_stage = [&](int kb0, int s) {
        #pragma unroll
        for (int si = 0; si < 4; si++) {
            const int c   = tid + si * 256;
            const int mb  = c >> 7;
            const int kbl = (c >> 5) & 3;
            const int ln  = c & 31;
            cp_async16(As_u32 + (s * A_STAGE_H + c * 8) * 2,
                       Abf + (((size_t)(mrow0 + mb) * KB16 + kb0 + kbl) << 8) + ln * 8);
        }
        #pragma unroll
        for (int si = 0; si < 8; si++) {
            const int c   = tid + si * 256;
            const int nbp = c >> 7;
            const int kbl = (c >> 5) & 3;
            const int ln  = c & 31;
            cp_async16(Bs_u32 + (s * B_STAGE_H + c * 8) * 2,
                       Wbf + (((size_t)(nbp0 + nbp) * KB16 + kb0 + kbl) << 8) + ln * 8);
        }
        asm volatile("cp.async.commit_group;\n");
    };

    do_stage(0, 0);
    do_stage(4, 1);

    for (int it = 0; it < NIT; it++) {
        if (it + 1 < NIT) asm volatile("cp.async.wait_group 1;\n");
        else              asm volatile("cp.async.wait_group 0;\n");
        __syncthreads();

        if (it + 2 < NIT) do_stage((it + 2) * 4, (it + 2) % 3);

        const int s = it % 3;
        const uint4* As4 = (const uint4*)As + s * (A_STAGE_H / 8);
        const uint4* Bs4 = (const uint4*)Bs + s * (B_STAGE_H / 8);

        #pragma unroll
        for (int kb = 0; kb < 4; kb++) {
            uint4 afr[4];
            #pragma unroll
            for (int mi = 0; mi < 4; mi++)
                afr[mi] = As4[((warp_mb + mi) * 4 + kb) * 32 + lane];
            uint4 bfr[4];
            #pragma unroll
            for (int np = 0; np < 4; np++)
                bfr[np] = Bs4[((warp_nbp + np) * 4 + kb) * 32 + lane];
            #pragma unroll
            for (int mi = 0; mi < 4; mi++)
                #pragma unroll
                for (int np = 0; np < 4; np++) {
                    mma_bf16(d[mi][2 * np],     afr[mi], bfr[np].x, bfr[np].y);
                    mma_bf16(d[mi][2 * np + 1], afr[mi], bfr[np].z, bfr[np].w);
                }
        }
    }

    // epilogue: bias (fp32) -> bf16 store, segmented (row stride 768)
    #pragma unroll
    for (int mi = 0; mi < 4; mi++) {
        const int r0 = block_row + wm * 64 + mi * 16 + gid;
        const int r1 = r0 + 8;
        #pragma unroll
        for (int ni = 0; ni < 8; ni++) {
            const int cg = block_col + wn * 64 + ni * 8 + 2 * tig;
            const int cl = out_col_base + wn * 64 + ni * 8 + 2 * tig;
            const float b0 = bias[cg], b1 = bias[cg + 1];
            *(uint32_t*)&Cout[(size_t)r0 * D_DIM + cl] =
                pack_bf2(d[mi][ni][0] + b0, d[mi][ni][1] + b1);
            *(uint32_t*)&Cout[(size_t)r1 * D_DIM + cl] =
                pack_bf2(d[mi][ni][2] + b0, d[mi][ni][3] + b1);
        }
    }
}

// ---------------------------------------------------------------------------
// MMA flash-attention (proven) — bf16 in, bf16 CTX out. Unchanged.
// ---------------------------------------------------------------------------
#define QSTRIDE 68
#define KSTRIDE 68
#define VSTRIDE 72
#define ATT_SMEM_FLOATS (T_DIM * (QSTRIDE + KSTRIDE + VSTRIDE))
#define ATT_SMEM_BYTES  (ATT_SMEM_FLOATS * 4)   // 212992

__device__ __forceinline__ void mma_tf32(float* d, uint32_t a0, uint32_t a1,
                                         uint32_t a2, uint32_t a3,
                                         uint32_t b0, uint32_t b1)
{
    asm volatile(
        "mma.sync.aligned.m16n8k8.row.col.f32.tf32.tf32.f32 "
        "{%0,%1,%2,%3}, {%4,%5,%6,%7}, {%8,%9}, {%0,%1,%2,%3};\n"
        : "+f"(d[0]), "+f"(d[1]), "+f"(d[2]), "+f"(d[3])
        : "r"(a0), "r"(a1), "r"(a2), "r"(a3), "r"(b0), "r"(b1));
}

__device__ __forceinline__ void bf8_to_f8(uint4 u, float* f, float scale) {
    const __nv_bfloat162* h = reinterpret_cast<const __nv_bfloat162*>(&u);
    #pragma unroll
    for (int i = 0; i < 4; i++) {
        float2 p = __bfloat1622float2(h[i]);
        f[2*i]   = p.x * scale;
        f[2*i+1] = p.y * scale;
    }
}

__global__ __launch_bounds__(512)
void flash_attn_kernel(const __nv_bfloat16* __restrict__ Q,
                       const __nv_bfloat16* __restrict__ K,
                       const __nv_bfloat16* __restrict__ V,
                       const int*   __restrict__ num_turns,
                       __nv_bfloat16* __restrict__ CTX)
{
    const int b = blockIdx.x / NH_DIM;
    const int h = blockIdx.x % NH_DIM;

    extern __shared__ float sm[];
    float* Qs = sm;
    float* Ks = Qs + T_DIM * QSTRIDE;
    float* Vs = Ks + T_DIM * KSTRIDE;

    const size_t base = ((size_t)b * T_DIM * NH_DIM + h) * DH_DIM;
    const int tid = threadIdx.x;

    for (int idx = tid; idx < T_DIM * (DH_DIM / 8); idx += 512) {
        const int t  = idx >> 3;
        const int c8 = (idx & 7) * 8;
        const size_t g = base + (size_t)t * D_DIM + c8;
        float qf[8], kf[8], vf[8];
        bf8_to_f8(*(const uint4*)&Q[g], qf, 0.125f);
        bf8_to_f8(*(const uint4*)&K[g], kf, 1.0f);
        bf8_to_f8(*(const uint4*)&V[g], vf, 1.0f);
        *(float4*)&Qs[t * QSTRIDE + c8]     = make_float4(qf[0], qf[1], qf[2], qf[3]);
        *(float4*)&Qs[t * QSTRIDE + c8 + 4] = make_float4(qf[4], qf[5], qf[6], qf[7]);
        *(float4*)&Ks[t * KSTRIDE + c8]     = make_float4(kf[0], kf[1], kf[2], kf[3]);
        *(float4*)&Ks[t * KSTRIDE + c8 + 4] = make_float4(kf[4], kf[5], kf[6], kf[7]);
        *(float4*)&Vs[t * VSTRIDE + c8]     = make_float4(vf[0], vf[1], vf[2], vf[3]);
        *(float4*)&Vs[t * VSTRIDE + c8 + 4] = make_float4(vf[4], vf[5], vf[6], vf[7]);
    }
    __syncthreads();

    const int warp = tid >> 5;
    const int lane = tid & 31;
    const int gid  = lane >> 2;
    const int tig  = lane & 3;

    const int q0 = warp * 16 + gid;
    const int q1 = q0 + 8;
    const int ntv  = num_turns[b];
    const int lim0 = min(q0, ntv);
    const int lim1 = min(q1, ntv);

    const int lim_max = min(warp * 16 + 15, ntv);
    const int nch = (lim_max + 63) >> 6;

    float octx[8][4];
    #pragma unroll
    for (int i = 0; i < 8; i++)
        #pragma unroll
        for (int j = 0; j < 4; j++) octx[i][j] = 0.0f;
    float m0 = -1e30f, m1 = -1e30f, l0 = 0.0f, l1 = 0.0f;

    for (int ch = 0; ch < nch; ch++) {
        const int kbase = ch * 64;

        float s[8][4];
        #pragma unroll
        for (int i = 0; i < 8; i++)
            #pragma unroll
            for (int j = 0; j < 4; j++) s[i][j] = 0.0f;

        #pragma unroll
        for (int kt = 0; kt < 8; kt++) {
            const int dh = kt * 8;
            const uint32_t a0 = __float_as_uint(Qs[q0 * QSTRIDE + dh + tig]);
            const uint32_t a1 = __float_as_uint(Qs[q1 * QSTRIDE + dh + tig]);
            const uint32_t a2 = __float_as_uint(Qs[q0 * QSTRIDE + dh + tig + 4]);
            const uint32_t a3 = __float_as_uint(Qs[q1 * QSTRIDE + dh + tig + 4]);
            #pragma unroll
            for (int nt8 = 0; nt8 < 8; nt8++) {
                const int krow = kbase + nt8 * 8 + gid;
                const uint32_t b0 = __float_as_uint(Ks[krow * KSTRIDE + dh + tig]);
                const uint32_t b1 = __float_as_uint(Ks[krow * KSTRIDE + dh + tig + 4]);
                mma_tf32(s[nt8], a0, a1, a2, a3, b0, b1);
            }
        }

        float mx0 = -1e30f, mx1 = -1e30f;
        #pragma unroll
        for (int i = 0; i < 8; i++) {
            const int kc = kbase + i * 8 + 2 * tig;
            s[i][0] = (kc     < lim0) ? s[i][0] : -1e30f;
            s[i][1] = (kc + 1 < lim0) ? s[i][1] : -1e30f;
            s[i][2] = (kc     < lim1) ? s[i][2] : -1e30f;
            s[i][3] = (kc + 1 < lim1) ? s[i][3] : -1e30f;
            mx0 = fmaxf(mx0, fmaxf(s[i][0], s[i][1]));
            mx1 = fmaxf(mx1, fmaxf(s[i][2], s[i][3]));
        }
        mx0 = fmaxf(mx0, __shfl_xor_sync(0xFFFFFFFFu, mx0, 1));
        mx0 = fmaxf(mx0, __shfl_xor_sync(0xFFFFFFFFu, mx0, 2));
        mx1 = fmaxf(mx1, __shfl_xor_sync(0xFFFFFFFFu, mx1, 1));
        mx1 = fmaxf(mx1, __shfl_xor_sync(0xFFFFFFFFu, mx1, 2));

        const float nm0 = fmaxf(m0, mx0);
        const float nm1 = fmaxf(m1, mx1);
        const float corr0 = __expf(m0 - nm0);
        const float corr1 = __expf(m1 - nm1);
        m0 = nm0; m1 = nm1;
        l0 *= corr0; l1 *= corr1;
        #pragma unroll
        for (int i = 0; i < 8; i++) {
            octx[i][0] *= corr0; octx[i][1] *= corr0;
            octx[i][2] *= corr1; octx[i][3] *= corr1;
        }

        #pragma unroll
        for (int i = 0; i < 8; i++) {
            const float p0 = __expf(s[i][0] - m0);
            const float p1 = __expf(s[i][1] - m0);
            const float p2 = __expf(s[i][2] - m1);
            const float p3 = __expf(s[i][3] - m1);
            l0 += p0 + p1;  l1 += p2 + p3;
            s[i][0] = p0; s[i][1] = p1; s[i][2] = p2; s[i][3] = p3;
        }

        const int qb = lane & ~3;
        const int src  = qb | (tig >> 1);
        const int src2 = src + 2;
        const bool par = (tig & 1) != 0;
        #pragma unroll
        for (int kt = 0; kt < 8; kt++) {
            const float v00 = __shfl_sync(0xFFFFFFFFu, s[kt][0], src);
            const float v01 = __shfl_sync(0xFFFFFFFFu, s[kt][1], src);
            const float v10 = __shfl_sync(0xFFFFFFFFu, s[kt][2], src);
            const float v11 = __shfl_sync(0xFFFFFFFFu, s[kt][3], src);
            const float w00 = __shfl_sync(0xFFFFFFFFu, s[kt][0], src2);
            const float w01 = __shfl_sync(0xFFFFFFFFu, s[kt][1], src2);
            const float w10 = __shfl_sync(0xFFFFFFFFu, s[kt][2], src2);
            const float w11 = __shfl_sync(0xFFFFFFFFu, s[kt][3], src2);
            uint32_t a0 = __float_as_uint(par ? v01 : v00);
            uint32_t a1 = __float_as_uint(par ? v11 : v10);
            uint32_t a2 = __float_as_uint(par ? w01 : w00);
            uint32_t a3 = __float_as_uint(par ? w11 : w10);
            asm volatile("cvt.rna.tf32.f32 %0, %0;" : "+r"(a0));
            asm volatile("cvt.rna.tf32.f32 %0, %0;" : "+r"(a1));
            asm volatile("cvt.rna.tf32.f32 %0, %0;" : "+r"(a2));
            asm volatile("cvt.rna.tf32.f32 %0, %0;" : "+r"(a3));
            const int vr0 = kbase + kt * 8 + tig;
            #pragma unroll
            for (int ndh = 0; ndh < 8; ndh++) {
                const uint32_t b0 = __float_as_uint(Vs[vr0 * VSTRIDE + ndh * 8 + gid]);
                const uint32_t b1 = __float_as_uint(Vs[(vr0 + 4) * VSTRIDE + ndh * 8 + gid]);
                mma_tf32(octx[ndh], a0, a1, a2, a3, b0, b1);
            }
        }
    }

    l0 += __shfl_xor_sync(0xFFFFFFFFu, l0, 1);
    l0 += __shfl_xor_sync(0xFFFFFFFFu, l0, 2);
    l1 += __shfl_xor_sync(0xFFFFFFFFu, l1, 1);
    l1 += __shfl_xor_sync(0xFFFFFFFFu, l1, 2);
    const float inv0 = (lim0 > 0) ? 1.0f / l0 : 0.0f;
    const float inv1 = (lim1 > 0) ? 1.0f / l1 : 0.0f;

    __nv_bfloat16* o0 = &CTX[base + (size_t)q0 * D_DIM];
    __nv_bfloat16* o1 = &CTX[base + (size_t)q1 * D_DIM];
    #pragma unroll
    for (int ndh = 0; ndh < 8; ndh++) {
        const int c = ndh * 8 + 2 * tig;
        *(uint32_t*)&o0[c] = pack_bf2(octx[ndh][0] * inv0, octx[ndh][1] * inv0);
        *(uint32_t*)&o1[c] = pack_bf2(octx[ndh][2] * inv1, octx[ndh][3] * inv1);
    }
}

// ---------------------------------------------------------------------------
// Classifier (proven round 10): warp per 4 rows, transposed smem weights.
// ---------------------------------------------------------------------------
#define WPAD 772

__global__ __launch_bounds__(512)
void classifier_kernel(const float* __restrict__ H,
                       const __nv_bfloat16* __restrict__ CTX,
                       const float* __restrict__ Wc,
                       const float* __restrict__ bc,
                       const float* __restrict__ WoWc,
                       const float* __restrict__ boWc,
                       const int*   __restrict__ num_turns,
                       float* __restrict__ out_all,
                       float* __restrict__ out_final)
{
    __shared__ float Wtop[C_DIM * WPAD];
    __shared__ float Wbot[C_DIM * WPAD];

    for (int i = threadIdx.x; i < D_DIM * C_DIM; i += 512) {
        const int dd = i / C_DIM, cc = i % C_DIM;
        Wtop[cc * WPAD + dd] = Wc[i];
        Wbot[cc * WPAD + dd] = WoWc[i];
    }
    __syncthreads();

    const int warp = threadIdx.x >> 5;
    const int lane = threadIdx.x & 31;
    const int row0 = (blockIdx.x * 16 + warp) * 4;

    float acc[4][C_DIM];
    #pragma unroll
    for (int r = 0; r < 4; r++)
        #pragma unroll
        for (int c = 0; c < C_DIM; c++) acc[r][c] = 0.0f;

    #pragma unroll
    for (int i = 0; i < 6; i++) {
        const int off = (i * 32 + lane) * 4;
        float4 h4[4];
        #pragma unroll
        for (int r = 0; r < 4; r++)
            h4[r] = *(const float4*)&H[(size_t)(row0 + r) * D_DIM + off];
        #pragma unroll
        for (int c = 0; c < C_DIM; c++) {
            const float4 w = *(const float4*)&Wtop[c * WPAD + off];
            #pragma unroll
            for (int r = 0; r < 4; r++)
                acc[r][c] += h4[r].x * w.x + h4[r].y * w.y
                           + h4[r].z * w.z + h4[r].w * w.w;
        }
    }

    #pragma unroll
    for (int i = 0; i < 3; i++) {
        const int off = (i * 32 + lane) * 8;
        float cf[4][8];
        #pragma unroll
        for (int r = 0; r < 4; r++) {
            uint4 u = *(const uint4*)&CTX[(size_t)(row0 + r) * D_DIM + off];
            const __nv_bfloat162* hh = reinterpret_cast<const __nv_bfloat162*>(&u);
            #pragma unroll
            for (int p = 0; p < 4; p++) {
                float2 cv = __bfloat1622float2(hh[p]);
                cf[r][2*p]   = cv.x;
                cf[r][2*p+1] = cv.y;
            }
        }
        #pragma unroll
        for (int c = 0; c < C_DIM; c++) {
            const float4 w0 = *(const float4*)&Wbot[c * WPAD + off];
            const float4 w1 = *(const float4*)&Wbot[c * WPAD + off + 4];
            #pragma unroll
            for (int r = 0; r < 4; r++)
                acc[r][c] += cf[r][0] * w0.x + cf[r][1] * w0.y
                           + cf[r][2] * w0.z + cf[r][3] * w0.w
                           + cf[r][4] * w1.x + cf[r][5] * w1.y
                           + cf[r][6] * w1.z + cf[r][7] * w1.w;
        }
    }

    #pragma unroll
    for (int r = 0; r < 4; r++)
        #pragma unroll
        for (int c = 0; c < C_DIM; c++) {
            acc[r][c] += __shfl_xor_sync(0xFFFFFFFFu, acc[r][c], 16);
            acc[r][c] += __shfl_xor_sync(0xFFFFFFFFu, acc[r][c], 8);
            acc[r][c] += __shfl_xor_sync(0xFFFFFFFFu, acc[r][c], 4);
            acc[r][c] += __shfl_xor_sync(0xFFFFFFFFu, acc[r][c], 2);
            acc[r][c] += __shfl_xor_sync(0xFFFFFFFFu, acc[r][c], 1);
        }

    if (lane == 0) {
        #pragma unroll
        for (int r = 0; r < 4; r++) {
            const int row = row0 + r;
            const int t = row & (T_DIM - 1);
            const int b = row >> 8;
            float* o = &out_all[(size_t)row * C_DIM];
            const bool fin = (t == num_turns[b] - 1);
            float* f = &out_final[(size_t)b * C_DIM];
            #pragma unroll
            for (int c = 0; c < C_DIM; c++) {
                const float v = acc[r][c] + bc[c] + ((t > 0) ? boWc[c] : 0.0f);
                o[c] = v;
                if (fin) f[c] = v;
            }
        }
    }
}

// ---------------------------------------------------------------------------
// Launch
// ---------------------------------------------------------------------------
extern "C" void kernel_launch(void* const* d_in, const int* in_sizes, int n_in,
                              void* d_out, int out_size)
{
    const float* H  = (const float*)d_in[0];
    const float* Wq = (const float*)d_in[1];
    const float* bq = (const float*)d_in[2];
    const float* Wk = (const float*)d_in[3];
    const float* bk = (const float*)d_in[4];
    const float* Wv = (const float*)d_in[5];
    const float* bv = (const float*)d_in[6];
    const float* Wo = (const float*)d_in[7];
    const float* bo = (const float*)d_in[8];
    const float* Wc = (const float*)d_in[9];
    const float* bc = (const float*)d_in[10];
    const int*   nt = (const int*)  d_in[11];

    float* out_all   = (float*)d_out;
    float* out_final = (float*)d_out + (size_t)B_DIM * T_DIM * C_DIM;

    float *bp, *WoWcb, *boWcb;
    __nv_bfloat16 *Qb, *Kb, *Vb, *CTXb, *Abf, *Wbf;
    cudaGetSymbolAddress((void**)&Qb,    g_Q);
    cudaGetSymbolAddress((void**)&Kb,    g_K);
    cudaGetSymbolAddress((void**)&Vb,    g_V);
    cudaGetSymbolAddress((void**)&CTXb,  g_CTX);
    cudaGetSymbolAddress((void**)&Abf,   g_Abf);
    cudaGetSymbolAddress((void**)&Wbf,   g_Wbf);
    cudaGetSymbolAddress((void**)&bp,    g_bpack);
    cudaGetSymbolAddress((void**)&WoWcb, g_WoWc);
    cudaGetSymbolAddress((void**)&boWcb, g_boWc);

    // 1) fused prep
    prep_kernel<<<PREP_BLOCKS, 256>>>(H, Wq, Wk, Wv, bq, bk, bv, Wo, Wc, bo,
                                      Abf, Wbf, bp, WoWcb, boWcb);

    // 2) fused QKV projection (bf16 tensor cores, 64x64 warp tiles)
    cudaFuncSetAttribute(bf16_gemm_kernel,
                         cudaFuncAttributeMaxDynamicSharedMemorySize, GEMM_SMEM_BYTES);
    {
        dim3 grid(NQKV / GBN, M_ROWS / GBM);   // (9, 128)
        bf16_gemm_kernel<<<grid, 256, GEMM_SMEM_BYTES>>>(Abf, Wbf, bp, Qb, Kb, Vb);
    }

    // 3) MMA flash attention
    cudaFuncSetAttribute(flash_attn_kernel,
                         cudaFuncAttributeMaxDynamicSharedMemorySize, ATT_SMEM_BYTES);
    flash_attn_kernel<<<B_DIM * NH_DIM, 512, ATT_SMEM_BYTES>>>(Qb, Kb, Vb, nt, CTXb);

    // 4) classifier + final gather
    classifier_kernel<<<M_ROWS / 64, 512>>>(H, CTXb, Wc, bc, WoWcb, boWcb,
                                            nt, out_all, out_final);
}

// round 13
// speedup vs baseline: 1.0744x; 1.0744x over previous
#include <cuda_runtime.h>
#include <cuda_bf16.h>
#include <math.h>
#include <stdint.h>

// Problem constants
#define B_DIM  64
#define T_DIM  256
#define D_DIM  768
#define NH_DIM 12
#define DH_DIM 64
#define C_DIM  7
#define M_ROWS (B_DIM * T_DIM)   // 16384
#define NQKV   (3 * D_DIM)       // 2304
#define KB16   (D_DIM / 16)      // 48
#define MB16   (M_ROWS / 16)     // 1024
#define NB8    (NQKV / 8)        // 288

// Prep-kernel block ranges
#define PA_BLOCKS  (MB16 * KB16 * 32 / 256)   // 6144
#define PW_BLOCKS  (NB8  * KB16 * 32 / 256)   // 1728
#define WC_BLOCKS  24
#define PREP_BLOCKS (PA_BLOCKS + PW_BLOCKS + WC_BLOCKS)

// ---------------------------------------------------------------------------
// Scratch (device globals; no runtime allocation allowed)
// ---------------------------------------------------------------------------
__device__ __nv_bfloat16 g_Q[(size_t)M_ROWS * D_DIM];
__device__ __nv_bfloat16 g_K[(size_t)M_ROWS * D_DIM];
__device__ __nv_bfloat16 g_V[(size_t)M_ROWS * D_DIM];
__device__ __nv_bfloat16 g_CTX[(size_t)M_ROWS * D_DIM];
__device__ __nv_bfloat16 g_Abf[(size_t)MB16 * KB16 * 256];
__device__ __nv_bfloat16 g_Wbf[(size_t)NB8  * KB16 * 128];
__device__ float g_bpack[NQKV];
__device__ float g_WoWc[D_DIM * C_DIM];
__device__ float g_boWc[C_DIM];

// ---------------------------------------------------------------------------
__device__ __forceinline__ uint32_t pack_bf2(float lo, float hi) {
    __nv_bfloat162 t = __floats2bfloat162_rn(lo, hi);
    return *reinterpret_cast<uint32_t*>(&t);
}

// ---------------------------------------------------------------------------
// Fused prep: pack A fragments | pack W fragments + biases | WoWc fold.
// (round 10, proven)
// ---------------------------------------------------------------------------
__global__ __launch_bounds__(256)
void prep_kernel(const float* __restrict__ H,
                 const float* __restrict__ Wq, const float* __restrict__ Wk,
                 const float* __restrict__ Wv,
                 const float* __restrict__ bq, const float* __restrict__ bk,
                 const float* __restrict__ bv,
                 const float* __restrict__ Wo, const float* __restrict__ Wc,
                 const float* __restrict__ bo,
                 __nv_bfloat16* __restrict__ Abf,
                 __nv_bfloat16* __restrict__ Wbf,
                 float* __restrict__ bp,
                 float* __restrict__ WoWc, float* __restrict__ boWc)
{
    const int blk = blockIdx.x;

    if (blk < PA_BLOCKS) {
        const int idx  = blk * 256 + threadIdx.x;
        const int lane = idx & 31;
        const int kblk = (idx >> 5) % KB16;
        const int mblk = idx / (KB16 * 32);
        const int gid  = lane >> 2;
        const int tig  = lane & 3;
        const int m0 = mblk * 16 + gid;
        const int k0 = kblk * 16 + 2 * tig;

        float2 p00 = *(const float2*)&H[(size_t)m0 * D_DIM + k0];
        float2 p10 = *(const float2*)&H[(size_t)(m0 + 8) * D_DIM + k0];
        float2 p01 = *(const float2*)&H[(size_t)m0 * D_DIM + k0 + 8];
        float2 p11 = *(const float2*)&H[(size_t)(m0 + 8) * D_DIM + k0 + 8];

        uint4 out;
        out.x = pack_bf2(p00.x, p00.y);
        out.y = pack_bf2(p10.x, p10.y);
        out.z = pack_bf2(p01.x, p01.y);
        out.w = pack_bf2(p11.x, p11.y);
        *(uint4*)&Abf[(size_t)idx * 8] = out;

    } else if (blk < PA_BLOCKS + PW_BLOCKS) {
        const int idx  = (blk - PA_BLOCKS) * 256 + threadIdx.x;
        const int lane = idx & 31;
        const int kblk = (idx >> 5) % KB16;
        const int nblk = idx / (KB16 * 32);
        const int gid  = lane >> 2;
        const int tig  = lane & 3;
        const int n  = nblk * 8 + gid;
        const int k0 = kblk * 16 + 2 * tig;

        const float* W = (n < D_DIM) ? Wq : ((n < 2 * D_DIM) ? Wk : Wv);
        const int j = (n >= 2 * D_DIM) ? (n - 2 * D_DIM)
                     : ((n >= D_DIM) ? (n - D_DIM) : n);

        const float w0 = W[(size_t)k0 * D_DIM + j];
        const float w1 = W[(size_t)(k0 + 1) * D_DIM + j];
        const float w2 = W[(size_t)(k0 + 8) * D_DIM + j];
        const float w3 = W[(size_t)(k0 + 9) * D_DIM + j];

        uint2 out;
        out.x = pack_bf2(w0, w1);
        out.y = pack_bf2(w2, w3);
        *(uint2*)&Wbf[(size_t)idx * 4] = out;

        if (idx < NQKV) {
            float bv_;
            if (idx < D_DIM)            bv_ = bq[idx];
            else if (idx < 2 * D_DIM)   bv_ = bk[idx - D_DIM];
            else                        bv_ = bv[idx - 2 * D_DIM];
            bp[idx] = bv_;
        }

    } else {
        const int wblk   = blk - PA_BLOCKS - PW_BLOCKS;
        const int gwarp  = (wblk * 256 + threadIdx.x) >> 5;
        const int nwarps = (WC_BLOCKS * 256) >> 5;
        const int lane   = threadIdx.x & 31;

        for (int d = gwarp; d < D_DIM; d += nwarps) {
            float acc[C_DIM];
            #pragma unroll
            for (int c = 0; c < C_DIM; c++) acc[c] = 0.0f;
            for (int n = lane; n < D_DIM; n += 32) {
                const float w = Wo[(size_t)d * D_DIM + n];
                const float* wcr = &Wc[(size_t)(D_DIM + n) * C_DIM];
                #pragma unroll
                for (int c = 0; c < C_DIM; c++) acc[c] += w * wcr[c];
            }
            #pragma unroll
            for (int c = 0; c < C_DIM; c++) {
                acc[c] += __shfl_xor_sync(0xFFFFFFFFu, acc[c], 16);
                acc[c] += __shfl_xor_sync(0xFFFFFFFFu, acc[c], 8);
                acc[c] += __shfl_xor_sync(0xFFFFFFFFu, acc[c], 4);
                acc[c] += __shfl_xor_sync(0xFFFFFFFFu, acc[c], 2);
                acc[c] += __shfl_xor_sync(0xFFFFFFFFu, acc[c], 1);
            }
            if (lane == 0) {
                #pragma unroll
                for (int c = 0; c < C_DIM; c++) WoWc[d * C_DIM + c] = acc[c];
            }
        }

        const int g = wblk * 256 + threadIdx.x;
        if (g < C_DIM) {
            float a = 0.0f;
            for (int n = 0; n < D_DIM; n++)
                a += bo[n] * Wc[(size_t)(D_DIM + n) * C_DIM + g];
            boWc[g] = a;
        }
    }
}

// ---------------------------------------------------------------------------
// BF16 tensor-core GEMM (round 10, proven): BK=64, 3-stage, warp tile 32x64.
// ---------------------------------------------------------------------------
#define A_STAGE_H 8192
#define B_STAGE_H 8192
#define GEMM_SMEM_BYTES (3 * (A_STAGE_H + B_STAGE_H) * 2)  // 98304

__device__ __forceinline__ void cp_async16(uint32_t smem_addr, const void* gptr) {
    asm volatile("cp.async.cg.shared.global [%0], [%1], 16;\n"
                 :: "r"(smem_addr), "l"(gptr));
}

__device__ __forceinline__ void mma_bf16_r(float* d,
                                           uint32_t a0, uint32_t a1,
                                           uint32_t a2, uint32_t a3,
                                           uint32_t b0, uint32_t b1) {
    asm volatile(
        "mma.sync.aligned.m16n8k16.row.col.f32.bf16.bf16.f32 "
        "{%0,%1,%2,%3}, {%4,%5,%6,%7}, {%8,%9}, {%0,%1,%2,%3};\n"
        : "+f"(d[0]), "+f"(d[1]), "+f"(d[2]), "+f"(d[3])
        : "r"(a0), "r"(a1), "r"(a2), "r"(a3), "r"(b0), "r"(b1));
}

__global__ __launch_bounds__(256)
void bf16_gemm_kernel(const __nv_bfloat16* __restrict__ Abf,
                      const __nv_bfloat16* __restrict__ Wbf,
                      const float* __restrict__ bias,
                      __nv_bfloat16* __restrict__ C0,
                      __nv_bfloat16* __restrict__ C1,
                      __nv_bfloat16* __restrict__ C2)
{
    extern __shared__ __nv_bfloat16 smem[];
    __nv_bfloat16* As = smem;
    __nv_bfloat16* Bs = smem + 3 * A_STAGE_H;

    const int tid  = threadIdx.x;
    const int lane = tid & 31;
    const int warp = tid >> 5;
    const int gid  = lane >> 2;
    const int tig  = lane & 3;

    const int mrow0 = blockIdx.y * 8;
    const int nb0   = blockIdx.x * 16;
    const int block_row = blockIdx.y * 128;
    const int block_col = blockIdx.x * 128;

    const int seg = block_col / D_DIM;
    __nv_bfloat16* Cout = (seg == 0) ? C0 : (seg == 1 ? C1 : C2);
    const int out_col_base = block_col - seg * D_DIM;

    const uint32_t As_u32 = (uint32_t)__cvta_generic_to_shared(As);
    const uint32_t Bs_u32 = As_u32 + 3 * A_STAGE_H * 2;

    float d[2][8][4];
    #pragma unroll
    for (int mi = 0; mi < 2; mi++)
        #pragma unroll
        for (int ni = 0; ni < 8; ni++)
            #pragma unroll
            for (int e = 0; e < 4; e++)
                d[mi][ni][e] = 0.0f;

    const int NITER = KB16 / 4;   // 12

    auto do_stage = [&](int kb0, int s) {
        #pragma unroll
        for (int si = 0; si < 4; si++) {
            const int c   = tid + si * 256;
            const int mb  = c >> 7;
            const int kbl = (c >> 5) & 3;
            const int ch  = c & 31;
            cp_async16(As_u32 + (s * A_STAGE_H + c * 8) * 2,
                       Abf + (((size_t)(mrow0 + mb) * KB16 + kb0 + kbl) << 8) + ch * 8);
        }
        #pragma unroll
        for (int si = 0; si < 4; si++) {
            const int c   = tid + si * 256;
            const int nb  = c >> 6;
            const int kbl = (c >> 4) & 3;
            const int ch  = c & 15;
            cp_async16(Bs_u32 + (s * B_STAGE_H + c * 8) * 2,
                       Wbf + (((size_t)(nb0 + nb) * KB16 + kb0 + kbl) << 7) + ch * 8);
        }
        asm volatile("cp.async.commit_group;\n");
    };

    do_stage(0, 0);
    do_stage(4, 1);

    const int warp_mb = (warp & 3) * 2;
    const int warp_nb = (warp >> 2) * 8;

    for (int it = 0; it < NITER; it++) {
        if (it + 1 < NITER) asm volatile("cp.async.wait_group 1;\n");
        else                asm volatile("cp.async.wait_group 0;\n");
        __syncthreads();

        if (it + 2 < NITER) do_stage((it + 2) * 4, (it + 2) % 3);

        const int s = it % 3;
        const uint4* As4 = (const uint4*)As + s * (A_STAGE_H / 8);
        const uint2* Bs2 = (const uint2*)Bs + s * (B_STAGE_H / 4);

        #pragma unroll
        for (int kb = 0; kb < 4; kb++) {
            uint4 afr[2];
            #pragma unroll
            for (int mi = 0; mi < 2; mi++)
                afr[mi] = As4[((warp_mb + mi) * 4 + kb) * 32 + lane];
            uint2 bfr[8];
            #pragma unroll
            for (int ni = 0; ni < 8; ni++)
                bfr[ni] = Bs2[((warp_nb + ni) * 4 + kb) * 32 + lane];
            #pragma unroll
            for (int mi = 0; mi < 2; mi++)
                #pragma unroll
                for (int ni = 0; ni < 8; ni++)
                    mma_bf16_r(d[mi][ni], afr[mi].x, afr[mi].y, afr[mi].z,
                               afr[mi].w, bfr[ni].x, bfr[ni].y);
        }
    }

    #pragma unroll
    for (int mi = 0; mi < 2; mi++) {
        const int r0 = block_row + (warp & 3) * 32 + mi * 16 + gid;
        const int r1 = r0 + 8;
        #pragma unroll
        for (int ni = 0; ni < 8; ni++) {
            const int cg = block_col + (warp >> 2) * 64 + ni * 8 + 2 * tig;
            const int cl = out_col_base + (warp >> 2) * 64 + ni * 8 + 2 * tig;
            const float b0 = bias[cg], b1 = bias[cg + 1];
            *(uint32_t*)&Cout[(size_t)r0 * D_DIM + cl] =
                pack_bf2(d[mi][ni][0] + b0, d[mi][ni][1] + b1);
            *(uint32_t*)&Cout[(size_t)r1 * D_DIM + cl] =
                pack_bf2(d[mi][ni][2] + b0, d[mi][ni][3] + b1);
        }
    }
}

// ---------------------------------------------------------------------------
// BF16 flash-attention v2: bf16 smem staging, m16n8k16 bf16 MMAs,
// direct P-fragment packing (no shuffles), Vt transposed for B fragments.
//   Qs,Ks: [256][72] bf16 (stride 72 halves -> frag loads conflict-free)
//   Vt:    [64][264] bf16 (stride 264 halves -> B frag loads conflict-free)
// ---------------------------------------------------------------------------
#define AQ_ST 72
#define AV_ST 264
#define ATT_SMEM_BYTES ((2 * T_DIM * AQ_ST + DH_DIM * AV_ST) * 2)  // 107520

__global__ __launch_bounds__(512)
void flash_attn_kernel(const __nv_bfloat16* __restrict__ Q,
                       const __nv_bfloat16* __restrict__ K,
                       const __nv_bfloat16* __restrict__ V,
                       const int*   __restrict__ num_turns,
                       __nv_bfloat16* __restrict__ CTX)
{
    const int b = blockIdx.x / NH_DIM;
    const int h = blockIdx.x % NH_DIM;

    extern __shared__ __nv_bfloat16 asm_[];
    __nv_bfloat16* Qs = asm_;                       // [256][AQ_ST]
    __nv_bfloat16* Ks = Qs + T_DIM * AQ_ST;         // [256][AQ_ST]
    __nv_bfloat16* Vt = Ks + T_DIM * AQ_ST;         // [64][AV_ST]

    const size_t base = ((size_t)b * T_DIM * NH_DIM + h) * DH_DIM;
    const int tid = threadIdx.x;

    // stage Q (scaled by 1/8, exact) and K: row t, 8-half chunk c8
    for (int idx = tid; idx < T_DIM * 8; idx += 512) {
        const int t  = idx >> 3;
        const int c8 = (idx & 7) * 8;
        const size_t g = base + (size_t)t * D_DIM + c8;
        uint4 qu = *(const uint4*)&Q[g];
        // scale Q by 0.125 (power of two -> exact in bf16)
        const __nv_bfloat162 sc = __floats2bfloat162_rn(0.125f, 0.125f);
        __nv_bfloat162* qh = reinterpret_cast<__nv_bfloat162*>(&qu);
        #pragma unroll
        for (int i = 0; i < 4; i++) qh[i] = __hmul2(qh[i], sc);
        *(uint4*)&Qs[t * AQ_ST + c8] = qu;
        *(uint4*)&Ks[t * AQ_ST + c8] = *(const uint4*)&K[g];
    }
    // stage V transposed: Vt[dh][key], key pairs packed per u32
    for (int idx = tid; idx < (T_DIM / 2) * 8; idx += 512) {
        const int tp = idx >> 3;          // key pair
        const int c8 = (idx & 7) * 8;
        const int t0 = tp * 2;
        const uint4 v0 = *(const uint4*)&V[base + (size_t)t0 * D_DIM + c8];
        const uint4 v1 = *(const uint4*)&V[base + (size_t)(t0 + 1) * D_DIM + c8];
        const uint16_t* h0 = reinterpret_cast<const uint16_t*>(&v0);
        const uint16_t* h1 = reinterpret_cast<const uint16_t*>(&v1);
        #pragma unroll
        for (int j = 0; j < 8; j++) {
            const uint32_t pr = (uint32_t)h0[j] | ((uint32_t)h1[j] << 16);
            *(uint32_t*)&Vt[(c8 + j) * AV_ST + t0] = pr;
        }
    }
    __syncthreads();

    const int warp = tid >> 5;
    const int lane = tid & 31;
    const int gid  = lane >> 2;
    const int tig  = lane & 3;

    const int q0 = warp * 16 + gid;
    const int q1 = q0 + 8;
    const int ntv  = num_turns[b];
    const int lim0 = min(q0, ntv);
    const int lim1 = min(q1, ntv);

    const int lim_max = min(warp * 16 + 15, ntv);
    const int nch = (lim_max + 63) >> 6;

    float octx[8][4];
    #pragma unroll
    for (int i = 0; i < 8; i++)
        #pragma unroll
        for (int j = 0; j < 4; j++) octx[i][j] = 0.0f;
    float m0 = -1e30f, m1 = -1e30f, l0 = 0.0f, l1 = 0.0f;

    for (int ch = 0; ch < nch; ch++) {
        const int kbase = ch * 64;

        // ---- S = Q Kchunk^T (bf16 k16 MMAs)
        float s[8][4];
        #pragma unroll
        for (int i = 0; i < 8; i++)
            #pragma unroll
            for (int j = 0; j < 4; j++) s[i][j] = 0.0f;

        #pragma unroll
        for (int kt = 0; kt < 4; kt++) {
            const int dh = kt * 16;
            const uint32_t a0 = *(const uint32_t*)&Qs[q0 * AQ_ST + dh + 2 * tig];
            const uint32_t a1 = *(const uint32_t*)&Qs[q1 * AQ_ST + dh + 2 * tig];
            const uint32_t a2 = *(const uint32_t*)&Qs[q0 * AQ_ST + dh + 8 + 2 * tig];
            const uint32_t a3 = *(const uint32_t*)&Qs[q1 * AQ_ST + dh + 8 + 2 * tig];
            #pragma unroll
            for (int nt8 = 0; nt8 < 8; nt8++) {
                const int krow = kbase + nt8 * 8 + gid;
                const uint32_t b0 = *(const uint32_t*)&Ks[krow * AQ_ST + dh + 2 * tig];
                const uint32_t b1 = *(const uint32_t*)&Ks[krow * AQ_ST + dh + 8 + 2 * tig];
                mma_bf16_r(s[nt8], a0, a1, a2, a3, b0, b1);
            }
        }

        // ---- mask + row max
        float mx0 = -1e30f, mx1 = -1e30f;
        #pragma unroll
        for (int i = 0; i < 8; i++) {
            const int kc = kbase + i * 8 + 2 * tig;
            s[i][0] = (kc     < lim0) ? s[i][0] : -1e30f;
            s[i][1] = (kc + 1 < lim0) ? s[i][1] : -1e30f;
            s[i][2] = (kc     < lim1) ? s[i][2] : -1e30f;
            s[i][3] = (kc + 1 < lim1) ? s[i][3] : -1e30f;
            mx0 = fmaxf(mx0, fmaxf(s[i][0], s[i][1]));
            mx1 = fmaxf(mx1, fmaxf(s[i][2], s[i][3]));
        }
        mx0 = fmaxf(mx0, __shfl_xor_sync(0xFFFFFFFFu, mx0, 1));
        mx0 = fmaxf(mx0, __shfl_xor_sync(0xFFFFFFFFu, mx0, 2));
        mx1 = fmaxf(mx1, __shfl_xor_sync(0xFFFFFFFFu, mx1, 1));
        mx1 = fmaxf(mx1, __shfl_xor_sync(0xFFFFFFFFu, mx1, 2));

        const float nm0 = fmaxf(m0, mx0);
        const float nm1 = fmaxf(m1, mx1);
        const float corr0 = __expf(m0 - nm0);
        const float corr1 = __expf(m1 - nm1);
        m0 = nm0; m1 = nm1;
        l0 *= corr0; l1 *= corr1;
        #pragma unroll
        for (int i = 0; i < 8; i++) {
            octx[i][0] *= corr0; octx[i][1] *= corr0;
            octx[i][2] *= corr1; octx[i][3] *= corr1;
        }

        // ---- P = exp(S - m); accumulate l
        #pragma unroll
        for (int i = 0; i < 8; i++) {
            const float p0 = __expf(s[i][0] - m0);
            const float p1 = __expf(s[i][1] - m0);
            const float p2 = __expf(s[i][2] - m1);
            const float p3 = __expf(s[i][3] - m1);
            l0 += p0 + p1;  l1 += p2 + p3;
            s[i][0] = p0; s[i][1] = p1; s[i][2] = p2; s[i][3] = p3;
        }

        // ---- ctx += P @ Vchunk: P fragments pack directly from accumulators
        #pragma unroll
        for (int kt16 = 0; kt16 < 4; kt16++) {
            const int i0 = 2 * kt16, i1 = i0 + 1;
            const uint32_t a0 = pack_bf2(s[i0][0], s[i0][1]);
            const uint32_t a1 = pack_bf2(s[i0][2], s[i0][3]);
            const uint32_t a2 = pack_bf2(s[i1][0], s[i1][1]);
            const uint32_t a3 = pack_bf2(s[i1][2], s[i1][3]);
            const int kb = kbase + kt16 * 16;
            #pragma unroll
            for (int ndh = 0; ndh < 8; ndh++) {
                const int vrow = ndh * 8 + gid;
                const uint32_t b0 = *(const uint32_t*)&Vt[vrow * AV_ST + kb + 2 * tig];
                const uint32_t b1 = *(const uint32_t*)&Vt[vrow * AV_ST + kb + 8 + 2 * tig];
                mma_bf16_r(octx[ndh], a0, a1, a2, a3, b0, b1);
            }
        }
    }

    l0 += __shfl_xor_sync(0xFFFFFFFFu, l0, 1);
    l0 += __shfl_xor_sync(0xFFFFFFFFu, l0, 2);
    l1 += __shfl_xor_sync(0xFFFFFFFFu, l1, 1);
    l1 += __shfl_xor_sync(0xFFFFFFFFu, l1, 2);
    const float inv0 = (lim0 > 0) ? 1.0f / l0 : 0.0f;
    const float inv1 = (lim1 > 0) ? 1.0f / l1 : 0.0f;

    __nv_bfloat16* o0 = &CTX[base + (size_t)q0 * D_DIM];
    __nv_bfloat16* o1 = &CTX[base + (size_t)q1 * D_DIM];
    #pragma unroll
    for (int ndh = 0; ndh < 8; ndh++) {
        const int c = ndh * 8 + 2 * tig;
        *(uint32_t*)&o0[c] = pack_bf2(octx[ndh][0] * inv0, octx[ndh][1] * inv0);
        *(uint32_t*)&o1[c] = pack_bf2(octx[ndh][2] * inv1, octx[ndh][3] * inv1);
    }
}

// ---------------------------------------------------------------------------
// Classifier (proven round 10): warp per 4 rows, transposed smem weights.
// ---------------------------------------------------------------------------
#define WPAD 772

__global__ __launch_bounds__(512)
void classifier_kernel(const float* __restrict__ H,
                       const __nv_bfloat16* __restrict__ CTX,
                       const float* __restrict__ Wc,
                       const float* __restrict__ bc,
                       const float* __restrict__ WoWc,
                       const float* __restrict__ boWc,
                       const int*   __restrict__ num_turns,
                       float* __restrict__ out_all,
                       float* __restrict__ out_final)
{
    __shared__ float Wtop[C_DIM * WPAD];
    __shared__ float Wbot[C_DIM * WPAD];

    for (int i = threadIdx.x; i < D_DIM * C_DIM; i += 512) {
        const int dd = i / C_DIM, cc = i % C_DIM;
        Wtop[cc * WPAD + dd] = Wc[i];
        Wbot[cc * WPAD + dd] = WoWc[i];
    }
    __syncthreads();

    const int warp = threadIdx.x >> 5;
    const int lane = threadIdx.x & 31;
    const int row0 = (blockIdx.x * 16 + warp) * 4;

    float acc[4][C_DIM];
    #pragma unroll
    for (int r = 0; r < 4; r++)
        #pragma unroll
        for (int c = 0; c < C_DIM; c++) acc[r][c] = 0.0f;

    #pragma unroll
    for (int i = 0; i < 6; i++) {
        const int off = (i * 32 + lane) * 4;
        float4 h4[4];
        #pragma unroll
        for (int r = 0; r < 4; r++)
            h4[r] = *(const float4*)&H[(size_t)(row0 + r) * D_DIM + off];
        #pragma unroll
        for (int c = 0; c < C_DIM; c++) {
            const float4 w = *(const float4*)&Wtop[c * WPAD + off];
            #pragma unroll
            for (int r = 0; r < 4; r++)
                acc[r][c] += h4[r].x * w.x + h4[r].y * w.y
                           + h4[r].z * w.z + h4[r].w * w.w;
        }
    }

    #pragma unroll
    for (int i = 0; i < 3; i++) {
        const int off = (i * 32 + lane) * 8;
        float cf[4][8];
        #pragma unroll
        for (int r = 0; r < 4; r++) {
            uint4 u = *(const uint4*)&CTX[(size_t)(row0 + r) * D_DIM + off];
            const __nv_bfloat162* hh = reinterpret_cast<const __nv_bfloat162*>(&u);
            #pragma unroll
            for (int p = 0; p < 4; p++) {
                float2 cv = __bfloat1622float2(hh[p]);
                cf[r][2*p]   = cv.x;
                cf[r][2*p+1] = cv.y;
            }
        }
        #pragma unroll
        for (int c = 0; c < C_DIM; c++) {
            const float4 w0 = *(const float4*)&Wbot[c * WPAD + off];
            const float4 w1 = *(const float4*)&Wbot[c * WPAD + off + 4];
            #pragma unroll
            for (int r = 0; r < 4; r++)
                acc[r][c] += cf[r][0] * w0.x + cf[r][1] * w0.y
                           + cf[r][2] * w0.z + cf[r][3] * w0.w
                           + cf[r][4] * w1.x + cf[r][5] * w1.y
                           + cf[r][6] * w1.z + cf[r][7] * w1.w;
        }
    }

    #pragma unroll
    for (int r = 0; r < 4; r++)
        #pragma unroll
        for (int c = 0; c < C_DIM; c++) {
            acc[r][c] += __shfl_xor_sync(0xFFFFFFFFu, acc[r][c], 16);
            acc[r][c] += __shfl_xor_sync(0xFFFFFFFFu, acc[r][c], 8);
            acc[r][c] += __shfl_xor_sync(0xFFFFFFFFu, acc[r][c], 4);
            acc[r][c] += __shfl_xor_sync(0xFFFFFFFFu, acc[r][c], 2);
            acc[r][c] += __shfl_xor_sync(0xFFFFFFFFu, acc[r][c], 1);
        }

    if (lane == 0) {
        #pragma unroll
        for (int r = 0; r < 4; r++) {
            const int row = row0 + r;
            const int t = row & (T_DIM - 1);
            const int b = row >> 8;
            float* o = &out_all[(size_t)row * C_DIM];
            const bool fin = (t == num_turns[b] - 1);
            float* f = &out_final[(size_t)b * C_DIM];
            #pragma unroll
            for (int c = 0; c < C_DIM; c++) {
                const float v = acc[r][c] + bc[c] + ((t > 0) ? boWc[c] : 0.0f);
                o[c] = v;
                if (fin) f[c] = v;
            }
        }
    }
}

// ---------------------------------------------------------------------------
// Launch
// ---------------------------------------------------------------------------
extern "C" void kernel_launch(void* const* d_in, const int* in_sizes, int n_in,
                              void* d_out, int out_size)
{
    const float* H  = (const float*)d_in[0];
    const float* Wq = (const float*)d_in[1];
    const float* bq = (const float*)d_in[2];
    const float* Wk = (const float*)d_in[3];
    const float* bk = (const float*)d_in[4];
    const float* Wv = (const float*)d_in[5];
    const float* bv = (const float*)d_in[6];
    const float* Wo = (const float*)d_in[7];
    const float* bo = (const float*)d_in[8];
    const float* Wc = (const float*)d_in[9];
    const float* bc = (const float*)d_in[10];
    const int*   nt = (const int*)  d_in[11];

    float* out_all   = (float*)d_out;
    float* out_final = (float*)d_out + (size_t)B_DIM * T_DIM * C_DIM;

    float *bp, *WoWcb, *boWcb;
    __nv_bfloat16 *Qb, *Kb, *Vb, *CTXb, *Abf, *Wbf;
    cudaGetSymbolAddress((void**)&Qb,    g_Q);
    cudaGetSymbolAddress((void**)&Kb,    g_K);
    cudaGetSymbolAddress((void**)&Vb,    g_V);
    cudaGetSymbolAddress((void**)&CTXb,  g_CTX);
    cudaGetSymbolAddress((void**)&Abf,   g_Abf);
    cudaGetSymbolAddress((void**)&Wbf,   g_Wbf);
    cudaGetSymbolAddress((void**)&bp,    g_bpack);
    cudaGetSymbolAddress((void**)&WoWcb, g_WoWc);
    cudaGetSymbolAddress((void**)&boWcb, g_boWc);

    // 1) fused prep
    prep_kernel<<<PREP_BLOCKS, 256>>>(H, Wq, Wk, Wv, bq, bk, bv, Wo, Wc, bo,
                                      Abf, Wbf, bp, WoWcb, boWcb);

    // 2) fused QKV projection (round-10 GEMM)
    cudaFuncSetAttribute(bf16_gemm_kernel,
                         cudaFuncAttributeMaxDynamicSharedMemorySize, GEMM_SMEM_BYTES);
    {
        dim3 grid(NQKV / 128, M_ROWS / 128);   // (18, 128)
        bf16_gemm_kernel<<<grid, 256, GEMM_SMEM_BYTES>>>(Abf, Wbf, bp, Qb, Kb, Vb);
    }

    // 3) bf16 flash attention (k16 MMAs, shuffle-free P)
    cudaFuncSetAttribute(flash_attn_kernel,
                         cudaFuncAttributeMaxDynamicSharedMemorySize, ATT_SMEM_BYTES);
    flash_attn_kernel<<<B_DIM * NH_DIM, 512, ATT_SMEM_BYTES>>>(Qb, Kb, Vb, nt, CTXb);

    // 4) classifier + final gather
    classifier_kernel<<<M_ROWS / 64, 512>>>(H, CTXb, Wc, bc, WoWcb, boWcb,
                                            nt, out_all, out_final);
}